// round 16
// baseline (speedup 1.0000x reference)
#include <cuda_runtime.h>
#include <cuda_bf16.h>
#include <float.h>
#include <stdint.h>

// Problem constants
#define BB     2
#define SS     2048
#define DD     2048
#define HH     16
#define HDIM   128
#define WINDOW 256
#define MROWS  (BB * SS)   // 4096
#define MD     ((long)MROWS * DD)

// ---------------------------------------------------------------------------
// Scratch (device globals — no allocation allowed)
// ---------------------------------------------------------------------------
__device__ float g_qkv[3 * MROWS * DD];       // q | k | v
__device__ float g_ao [MROWS * DD];           // rna(hs) first, then attn output
__device__ __nv_bfloat16 g_ahi[MROWS * DD];
__device__ __nv_bfloat16 g_alo[MROWS * DD];
__device__ __nv_bfloat16 g_whi[2 * DD * DD];  // Wq | Wk  (bf16 hi)
__device__ __nv_bfloat16 g_wlo[2 * DD * DD];  // Wq | Wk  (bf16 lo)
__device__ float g_wT[2 * DD * DD];           // WvT | WoT (tf32-rounded fp32)

// ---------------------------------------------------------------------------
// PTX helpers (family-wide only: harness emits compute_103 PTX -> no tcgen05)
// ---------------------------------------------------------------------------
__device__ __forceinline__ uint32_t smem_u32(const void* p) {
    uint32_t a;
    asm("{ .reg .u64 t; cvta.to.shared.u64 t, %1; cvt.u32.u64 %0, t; }"
        : "=r"(a) : "l"(p));
    return a;
}

__device__ __forceinline__ float rna_tf32(float x) {
    float y;
    asm("cvt.rna.tf32.f32 %0, %1;" : "=f"(y) : "f"(x));
    return y;
}

#define CP16(dst, src) \
    asm volatile("cp.async.cg.shared.global [%0], [%1], 16;" :: "r"(dst), "l"(src))
#define CP_COMMIT() asm volatile("cp.async.commit_group;" ::: "memory")
#define CP_WAIT1()  asm volatile("cp.async.wait_group 1;" ::: "memory")

#define LDSM_X4(r0, r1, r2, r3, addr) \
    asm volatile("ldmatrix.sync.aligned.m8n8.x4.shared.b16 {%0,%1,%2,%3}, [%4];" \
        : "=r"(r0), "=r"(r1), "=r"(r2), "=r"(r3) : "r"(addr))

#define LDSM_X4_T(r0, r1, r2, r3, addr) \
    asm volatile("ldmatrix.sync.aligned.m8n8.x4.trans.shared.b16 {%0,%1,%2,%3}, [%4];" \
        : "=r"(r0), "=r"(r1), "=r"(r2), "=r"(r3) : "r"(addr))

#define MMA16816(d, a, b) \
    asm volatile("mma.sync.aligned.m16n8k16.row.col.f32.bf16.bf16.f32 " \
        "{%0,%1,%2,%3}, {%4,%5,%6,%7}, {%8,%9}, {%0,%1,%2,%3};" \
        : "+f"((d)[0]), "+f"((d)[1]), "+f"((d)[2]), "+f"((d)[3]) \
        : "r"((a)[0]), "r"((a)[1]), "r"((a)[2]), "r"((a)[3]), \
          "r"((b)[0]), "r"((b)[1]))

#define MMA_TF32(d, a, b) \
    asm volatile("mma.sync.aligned.m16n8k8.row.col.f32.tf32.tf32.f32 " \
        "{%0,%1,%2,%3}, {%4,%5,%6,%7}, {%8,%9}, {%0,%1,%2,%3};" \
        : "+f"((d)[0]), "+f"((d)[1]), "+f"((d)[2]), "+f"((d)[3]) \
        : "r"((a)[0]), "r"((a)[1]), "r"((a)[2]), "r"((a)[3]), \
          "r"((b)[0]), "r"((b)[1]))

// ---------------------------------------------------------------------------
// Split fp32 -> bf16 hi + lo AND tf32-rounded fp32 copy (for the tf32 V gemm)
// ---------------------------------------------------------------------------
__global__ __launch_bounds__(256) void split3_kernel(
    const float* __restrict__ X, __nv_bfloat16* __restrict__ H,
    __nv_bfloat16* __restrict__ L, float* __restrict__ R, int n4)
{
    int i = blockIdx.x * blockDim.x + threadIdx.x;
    if (i >= n4) return;
    float4 x = ((const float4*)X)[i];
    __nv_bfloat16 h0 = __float2bfloat16(x.x);
    __nv_bfloat16 h1 = __float2bfloat16(x.y);
    __nv_bfloat16 h2 = __float2bfloat16(x.z);
    __nv_bfloat16 h3 = __float2bfloat16(x.w);
    __nv_bfloat16 l0 = __float2bfloat16(x.x - __bfloat162float(h0));
    __nv_bfloat16 l1 = __float2bfloat16(x.y - __bfloat162float(h1));
    __nv_bfloat16 l2 = __float2bfloat16(x.z - __bfloat162float(h2));
    __nv_bfloat16 l3 = __float2bfloat16(x.w - __bfloat162float(h3));
    ((__nv_bfloat162*)H)[2*i]   = __nv_bfloat162(h0, h1);
    ((__nv_bfloat162*)H)[2*i+1] = __nv_bfloat162(h2, h3);
    ((__nv_bfloat162*)L)[2*i]   = __nv_bfloat162(l0, l1);
    ((__nv_bfloat162*)L)[2*i+1] = __nv_bfloat162(l2, l3);
    float4 r = make_float4(rna_tf32(x.x), rna_tf32(x.y),
                           rna_tf32(x.z), rna_tf32(x.w));
    ((float4*)R)[i] = r;
}

// ---------------------------------------------------------------------------
// Weight prep, one launch: z 0..1 -> bf16 transposed split of Wq/Wk;
// z 2..3 -> tf32-rounded transpose of Wv/Wo.
// ---------------------------------------------------------------------------
__global__ __launch_bounds__(256) void wprep_kernel(
    const float* __restrict__ Wq, const float* __restrict__ Wk,
    const float* __restrict__ Wv, const float* __restrict__ Wo,
    __nv_bfloat16* __restrict__ TH, __nv_bfloat16* __restrict__ TL,
    float* __restrict__ T32)
{
    __shared__ float t[32][33];
    const int z = blockIdx.z;
    const float* W = (z == 0) ? Wq : (z == 1) ? Wk : (z == 2) ? Wv : Wo;
    const int n0 = blockIdx.x * 32, k0 = blockIdx.y * 32;
    const int tx = threadIdx.x & 31, ty = threadIdx.x >> 5;
    #pragma unroll
    for (int i = 0; i < 32; i += 8)
        t[ty + i][tx] = W[(long)(k0 + ty + i) * DD + n0 + tx];
    __syncthreads();
    if (z < 2) {
        __nv_bfloat16* th = TH + (long)z * DD * DD;
        __nv_bfloat16* tl = TL + (long)z * DD * DD;
        #pragma unroll
        for (int i = 0; i < 32; i += 8) {
            float x = t[tx][ty + i];
            long o = (long)(n0 + ty + i) * DD + k0 + tx;
            __nv_bfloat16 h = __float2bfloat16(x);
            th[o] = h;
            tl[o] = __float2bfloat16(x - __bfloat162float(h));
        }
    } else {
        float* out = T32 + (long)(z - 2) * DD * DD;
        #pragma unroll
        for (int i = 0; i < 32; i += 8)
            out[(long)(n0 + ty + i) * DD + k0 + tx] = rna_tf32(t[tx][ty + i]);
    }
}

// ---------------------------------------------------------------------------
// bf16x3 HMMA GEMM, packed-N weights (verified: 3-stage, 2 CTAs/SM).
// ---------------------------------------------------------------------------
#define GKB      64
#define GNIT     96
#define GPAD     72
#define G_OPB    (128 * GPAD * 2)
#define G_STAGEB (2 * G_OPB)
#define GSMEM_TOTAL (3 * G_STAGEB)        // 110592 B

__device__ __forceinline__ void g_load_stage(
    uint32_t sbase, int stage, int tid,
    const __nv_bfloat16* __restrict__ Asrc, const __nv_bfloat16* __restrict__ Bsrc,
    long row0, long bcol0, int kc)
{
    const uint32_t abase = sbase + stage * G_STAGEB;
    const uint32_t bbase = abase + G_OPB;
    const __nv_bfloat16* Ap = Asrc + row0 * DD + kc;
    const __nv_bfloat16* Bp = Bsrc + bcol0 * DD + kc;
    #pragma unroll
    for (int i = 0; i < 4; i++) {
        int idx = i * 256 + tid;
        int r  = idx >> 3;
        int ch = idx & 7;
        uint32_t so = (uint32_t)(r * (GPAD * 2) + ch * 16);
        CP16(abase + so, Ap + (long)r * DD + ch * 8);
        CP16(bbase + so, Bp + (long)r * DD + ch * 8);
    }
}

__global__ __launch_bounds__(256, 2) void gemm_bf16x3_kernel(
    const __nv_bfloat16* __restrict__ Ahi, const __nv_bfloat16* __restrict__ Alo,
    const __nv_bfloat16* __restrict__ Bhi, const __nv_bfloat16* __restrict__ Blo,
    const float* __restrict__ bias, float* __restrict__ Cbase)
{
    extern __shared__ char gsm[];
    const uint32_t sb = smem_u32(gsm);
    const int tid  = threadIdx.x;
    const int wid  = tid >> 5;
    const int lane = tid & 31;
    const long bcol0 = (long)blockIdx.x * 128;
    const long row0  = (long)blockIdx.y * 128;
    const int  which = (int)(bcol0 >> 11);           // 0..1 (Q,K)
    const long cc0   = bcol0 & 2047;
    float* C = Cbase + (long)which * MD;

    const int warp_m = (wid >> 1) * 32;
    const int warp_n = (wid & 1) * 64;
    const int lr = lane & 15;
    const int hl = lane >> 4;

    float acc[2][8][4];
    #pragma unroll
    for (int mt = 0; mt < 2; mt++)
        #pragma unroll
        for (int nt = 0; nt < 8; nt++)
            #pragma unroll
            for (int e = 0; e < 4; e++)
                acc[mt][nt][e] = 0.0f;

    g_load_stage(sb, 0, tid, Ahi, Bhi, row0, bcol0, 0);
    CP_COMMIT();
    g_load_stage(sb, 1, tid, Ahi, Bhi, row0, bcol0, GKB);
    CP_COMMIT();

    int s = 0, ps = 2;
    #pragma unroll 1
    for (int it = 0; it < GNIT; it++) {
        CP_WAIT1();
        __syncthreads();

        const int nit = it + 2;
        if (nit < GNIT) {
            const int pass = nit >> 5;
            const int kc = (nit & 31) * GKB;
            const __nv_bfloat16* As = (pass == 2) ? Alo : Ahi;
            const __nv_bfloat16* Bs = (pass == 1) ? Blo : Bhi;
            g_load_stage(sb, ps, tid, As, Bs, row0, bcol0, kc);
        }
        CP_COMMIT();

        const uint32_t sA = sb + s * G_STAGEB;
        const uint32_t sB = sA + G_OPB;
        #pragma unroll
        for (int ks = 0; ks < 4; ks++) {
            const int k0 = ks * 16;
            uint32_t aF[2][4], bF[8][2];
            #pragma unroll
            for (int mt = 0; mt < 2; mt++) {
                uint32_t addr = sA + (uint32_t)((warp_m + mt * 16 + lr) * (GPAD * 2)
                                              + (k0 + 8 * hl) * 2);
                LDSM_X4(aF[mt][0], aF[mt][1], aF[mt][2], aF[mt][3], addr);
            }
            #pragma unroll
            for (int nt2 = 0; nt2 < 4; nt2++) {
                uint32_t r0, r1, r2, r3;
                uint32_t addr = sB + (uint32_t)((warp_n + nt2 * 16 + lr) * (GPAD * 2)
                                              + (k0 + 8 * hl) * 2);
                LDSM_X4(r0, r1, r2, r3, addr);
                bF[2 * nt2][0]     = r0;
                bF[2 * nt2 + 1][0] = r1;
                bF[2 * nt2][1]     = r2;
                bF[2 * nt2 + 1][1] = r3;
            }
            #pragma unroll
            for (int mt = 0; mt < 2; mt++)
                #pragma unroll
                for (int nt = 0; nt < 8; nt++)
                    MMA16816(acc[mt][nt], aF[mt], bF[nt]);
        }
        s = (s == 2) ? 0 : s + 1;
        ps = (ps == 2) ? 0 : ps + 1;
    }

    const int erow = lane >> 2;
    const int ecol = (lane & 3) * 2;
    #pragma unroll
    for (int mt = 0; mt < 2; mt++) {
        #pragma unroll
        for (int nt = 0; nt < 8; nt++) {
            const long r  = row0 + warp_m + mt * 16 + erow;
            const long cc = cc0 + warp_n + nt * 8 + ecol;
            float b0 = bias ? bias[cc] : 0.0f;
            float b1 = bias ? bias[cc + 1] : 0.0f;
            float2 v0 = make_float2(acc[mt][nt][0] + b0, acc[mt][nt][1] + b1);
            float2 v1 = make_float2(acc[mt][nt][2] + b0, acc[mt][nt][3] + b1);
            *(float2*)(C + r * DD + cc)       = v0;
            *(float2*)(C + (r + 8) * DD + cc) = v1;
        }
    }
}

// ---------------------------------------------------------------------------
// Single-pass TF32 GEMM with ldmatrix fragments (verified round 10).
// ---------------------------------------------------------------------------
#define TKB   32
#define TNIT  64
#define TPAD  36
#define T_OPB (128 * TPAD * 4)
#define T_STAGEB (2 * T_OPB)
#define TSMEM_TOTAL (3 * T_STAGEB)        // 110592 B

__device__ __forceinline__ void t_load_stage(
    uint32_t sbase, int stage, int tid,
    const float* __restrict__ Asrc, const float* __restrict__ Bsrc,
    long row0, long col0, int kc)
{
    const uint32_t abase = sbase + stage * T_STAGEB;
    const uint32_t bbase = abase + T_OPB;
    const float* Ap = Asrc + row0 * DD + kc;
    const float* Bp = Bsrc + col0 * DD + kc;
    #pragma unroll
    for (int i = 0; i < 4; i++) {
        int idx = i * 256 + tid;
        int r  = idx >> 3;
        int ch = idx & 7;
        uint32_t so = (uint32_t)(r * (TPAD * 4) + ch * 16);
        CP16(abase + so, Ap + (long)r * DD + ch * 4);
        CP16(bbase + so, Bp + (long)r * DD + ch * 4);
    }
}

__global__ __launch_bounds__(256, 2) void gemm_tf32_kernel(
    const float* __restrict__ A, const float* __restrict__ Bt,
    const float* __restrict__ bias, float* __restrict__ C)
{
    extern __shared__ char tsm[];
    const uint32_t sb = smem_u32(tsm);
    const int tid  = threadIdx.x;
    const int wid  = tid >> 5;
    const int lane = tid & 31;
    const long col0 = (long)blockIdx.x * 128;
    const long row0 = (long)blockIdx.y * 128;

    const int warp_m = (wid >> 1) * 32;
    const int warp_n = (wid & 1) * 64;

    const int a_row = lane & 15;
    const int a_kof = (lane >> 4) * 4;
    const int b_row = (lane & 7) + ((lane >> 4) << 3);
    const int b_kof = ((lane >> 3) & 1) * 4;

    float acc[2][8][4];
    #pragma unroll
    for (int mt = 0; mt < 2; mt++)
        #pragma unroll
        for (int nt = 0; nt < 8; nt++)
            #pragma unroll
            for (int e = 0; e < 4; e++)
                acc[mt][nt][e] = 0.0f;

    t_load_stage(sb, 0, tid, A, Bt, row0, col0, 0);
    CP_COMMIT();
    t_load_stage(sb, 1, tid, A, Bt, row0, col0, TKB);
    CP_COMMIT();

    int s = 0, ps = 2;
    #pragma unroll 1
    for (int it = 0; it < TNIT; it++) {
        CP_WAIT1();
        __syncthreads();

        const int nit = it + 2;
        if (nit < TNIT)
            t_load_stage(sb, ps, tid, A, Bt, row0, col0, nit * TKB);
        CP_COMMIT();

        const uint32_t sA = sb + s * T_STAGEB;
        const uint32_t sB = sA + T_OPB;
        #pragma unroll
        for (int ks = 0; ks < 4; ks++) {
            const int k0 = ks * 8;
            uint32_t aF[2][4], bF[8][2];
            #pragma unroll
            for (int mt = 0; mt < 2; mt++) {
                uint32_t addr = sA + (uint32_t)((warp_m + mt * 16 + a_row) * (TPAD * 4)
                                              + (k0 + a_kof) * 4);
                LDSM_X4(aF[mt][0], aF[mt][1], aF[mt][2], aF[mt][3], addr);
            }
            #pragma unroll
            for (int nt2 = 0; nt2 < 4; nt2++) {
                uint32_t r0, r1, r2, r3;
                uint32_t addr = sB + (uint32_t)((warp_n + nt2 * 16 + b_row) * (TPAD * 4)
                                              + (k0 + b_kof) * 4);
                LDSM_X4(r0, r1, r2, r3, addr);
                bF[2 * nt2][0]     = r0;
                bF[2 * nt2][1]     = r1;
                bF[2 * nt2 + 1][0] = r2;
                bF[2 * nt2 + 1][1] = r3;
            }
            #pragma unroll
            for (int mt = 0; mt < 2; mt++)
                #pragma unroll
                for (int nt = 0; nt < 8; nt++)
                    MMA_TF32(acc[mt][nt], aF[mt], bF[nt]);
        }
        s = (s == 2) ? 0 : s + 1;
        ps = (ps == 2) ? 0 : ps + 1;
    }

    const int erow = lane >> 2;
    const int ecol = (lane & 3) * 2;
    #pragma unroll
    for (int mt = 0; mt < 2; mt++) {
        #pragma unroll
        for (int nt = 0; nt < 8; nt++) {
            const long r  = row0 + warp_m + mt * 16 + erow;
            const long cc = col0 + warp_n + nt * 8 + ecol;
            float b0 = bias ? bias[cc] : 0.0f;
            float b1 = bias ? bias[cc + 1] : 0.0f;
            float2 v0 = make_float2(acc[mt][nt][0] + b0, acc[mt][nt][1] + b1);
            float2 v1 = make_float2(acc[mt][nt][2] + b0, acc[mt][nt][3] + b1);
            *(float2*)(C + r * DD + cc)       = v0;
            *(float2*)(C + (r + 8) * DD + cc) = v1;
        }
    }
}

// ---------------------------------------------------------------------------
// Local-window attention — fully tensorized:
//   S = Qh*Kh + Qh*Kl + Ql*Kh   (HMMA, verified round 15)
//   O = Ph*Vh + Ph*Vl + Pl*Vh   (HMMA, NEW: V as B-operand via ldmatrix.trans)
// O lives in HMMA accumulator fragments across chunks; online-softmax rescale
// via per-row scl published to smem (scl_s).  P staged bf16 hi/lo pitch 72
// (verified GEMM addressing); V staged bf16 hi/lo [k][d] pitch 136 (verified
// conflict-free), trans-LDSM mapping: lane l of a k8xd8 tile gets
// V[k0+2(l%4)+i][d0+l/4] = b[n][k].  smem 140544 B, 1 CTA/SM.
// ---------------------------------------------------------------------------
#define BQ   64
#define BKC  64
#define SQP  136                           // Q/K/V bf16 row pitch (272 B)
#define PQP  72                            // P bf16 row pitch (144 B)
#define PP   68                            // PsT pitch in floats (272 B)
#define A_QH 0
#define A_QL (A_QH + 64 * SQP * 2)         // 17408
#define A_KH (A_QL + 64 * SQP * 2)         // 34816
#define A_KL (A_KH + 64 * SQP * 2)         // 52224
#define A_VH (A_KL + 64 * SQP * 2)         // 69632
#define A_VL (A_VH + 64 * SQP * 2)         // 87040
#define A_PH (A_VL + 64 * SQP * 2)         // 104448
#define A_PL (A_PH + 64 * PQP * 2)         // 113664
#define A_PS (A_PL + 64 * PQP * 2)         // 122880
#define A_SC (A_PS + 64 * PP * 4)          // 140288 (64 floats scl / linv)
#define ATT_SMEM_BYTES (A_SC + 64 * 4)     // 140544

__global__ __launch_bounds__(256, 1) void attn_local_kernel(
    const float* __restrict__ Q, const float* __restrict__ K,
    const float* __restrict__ V, const int* __restrict__ amask,
    float* __restrict__ O)
{
    const int q0 = blockIdx.x * BQ;
    const int h  = blockIdx.y;
    const int b  = blockIdx.z;

    extern __shared__ char asmem[];
    const uint32_t sb = smem_u32(asmem);
    __nv_bfloat16* Qh = (__nv_bfloat16*)(asmem + A_QH);
    __nv_bfloat16* Ql = (__nv_bfloat16*)(asmem + A_QL);
    __nv_bfloat16* Kh = (__nv_bfloat16*)(asmem + A_KH);
    __nv_bfloat16* Kl = (__nv_bfloat16*)(asmem + A_KL);
    __nv_bfloat16* Vh = (__nv_bfloat16*)(asmem + A_VH);
    __nv_bfloat16* Vl = (__nv_bfloat16*)(asmem + A_VL);
    __nv_bfloat16* Ph = (__nv_bfloat16*)(asmem + A_PH);
    __nv_bfloat16* Pl = (__nv_bfloat16*)(asmem + A_PL);
    float* PsT  = (float*)(asmem + A_PS);
    float* sc_s = (float*)(asmem + A_SC);

    const int tid  = threadIdx.x;
    const int wid  = tid >> 5;
    const int lane = tid & 31;
    const int r    = tid >> 4;             // softmax mapping (q rows r*4+i)
    const int c    = tid & 15;             // key cols c*4+j
    const int wm   = (wid & 3) * 16;       // S/PV warp tile rows (q)
    const int wn   = (wid >> 2) * 32;      // S warp tile cols (k)
    const int wn2  = (wid >> 2) * 64;      // PV warp tile cols (d)
    const int lr   = lane & 15;
    const int hl   = lane >> 4;
    // trans-LDSM lane addressing for V (B operand)
    const int vkr  = (lane & 7) + ((lane >> 3) & 1) * 8;   // k row within 16
    const int vdc  = (lane >> 4) * 8;                      // d col offset within 16

    // Q staging: fp32 -> bf16 hi/lo, pitch 136
    const float* qbase = Q + ((long)(b * SS + q0)) * DD + h * HDIM;
    #pragma unroll
    for (int e = tid; e < BQ * (HDIM / 4); e += 256) {
        int qi = e >> 5, d4 = e & 31;
        float4 f = *(const float4*)(qbase + (long)qi * DD + d4 * 4);
        __nv_bfloat16 h0 = __float2bfloat16(f.x), h1 = __float2bfloat16(f.y);
        __nv_bfloat16 h2 = __float2bfloat16(f.z), h3 = __float2bfloat16(f.w);
        *(__nv_bfloat162*)&Qh[qi * SQP + d4 * 4]     = __nv_bfloat162(h0, h1);
        *(__nv_bfloat162*)&Qh[qi * SQP + d4 * 4 + 2] = __nv_bfloat162(h2, h3);
        __nv_bfloat16 l0 = __float2bfloat16(f.x - __bfloat162float(h0));
        __nv_bfloat16 l1 = __float2bfloat16(f.y - __bfloat162float(h1));
        __nv_bfloat16 l2 = __float2bfloat16(f.z - __bfloat162float(h2));
        __nv_bfloat16 l3 = __float2bfloat16(f.w - __bfloat162float(h3));
        *(__nv_bfloat162*)&Ql[qi * SQP + d4 * 4]     = __nv_bfloat162(l0, l1);
        *(__nv_bfloat162*)&Ql[qi * SQP + d4 * 4 + 2] = __nv_bfloat162(l2, l3);
    }

    float m[4], l[4];
    float acco[8][4];                      // O fragments: warp tile 16 x 64
    #pragma unroll
    for (int i = 0; i < 4; i++) { m[i] = -FLT_MAX; l[i] = 0.0f; }
    #pragma unroll
    for (int nt = 0; nt < 8; nt++)
        #pragma unroll
        for (int e = 0; e < 4; e++) acco[nt][e] = 0.0f;

    for (int t = 0; t < 5; t++) {
        const int kb = q0 - WINDOW + t * BKC;
        if (kb < 0) continue;

        __syncthreads();   // prev chunk's MMAs done with K/V/P buffers

        // K + V staging (both bf16 hi/lo, pitch 136)
        const float* kbase = K + ((long)(b * SS + kb)) * DD + h * HDIM;
        const float* vbase = V + ((long)(b * SS + kb)) * DD + h * HDIM;
        #pragma unroll
        for (int e = tid; e < BKC * (HDIM / 4); e += 256) {
            int kj = e >> 5, d4 = e & 31;
            float4 kf = *(const float4*)(kbase + (long)kj * DD + d4 * 4);
            float4 vf = *(const float4*)(vbase + (long)kj * DD + d4 * 4);
            {
                __nv_bfloat16 h0 = __float2bfloat16(kf.x), h1 = __float2bfloat16(kf.y);
                __nv_bfloat16 h2 = __float2bfloat16(kf.z), h3 = __float2bfloat16(kf.w);
                *(__nv_bfloat162*)&Kh[kj * SQP + d4 * 4]     = __nv_bfloat162(h0, h1);
                *(__nv_bfloat162*)&Kh[kj * SQP + d4 * 4 + 2] = __nv_bfloat162(h2, h3);
                __nv_bfloat16 l0 = __float2bfloat16(kf.x - __bfloat162float(h0));
                __nv_bfloat16 l1 = __float2bfloat16(kf.y - __bfloat162float(h1));
                __nv_bfloat16 l2 = __float2bfloat16(kf.z - __bfloat162float(h2));
                __nv_bfloat16 l3 = __float2bfloat16(kf.w - __bfloat162float(h3));
                *(__nv_bfloat162*)&Kl[kj * SQP + d4 * 4]     = __nv_bfloat162(l0, l1);
                *(__nv_bfloat162*)&Kl[kj * SQP + d4 * 4 + 2] = __nv_bfloat162(l2, l3);
            }
            {
                __nv_bfloat16 h0 = __float2bfloat16(vf.x), h1 = __float2bfloat16(vf.y);
                __nv_bfloat16 h2 = __float2bfloat16(vf.z), h3 = __float2bfloat16(vf.w);
                *(__nv_bfloat162*)&Vh[kj * SQP + d4 * 4]     = __nv_bfloat162(h0, h1);
                *(__nv_bfloat162*)&Vh[kj * SQP + d4 * 4 + 2] = __nv_bfloat162(h2, h3);
                __nv_bfloat16 l0 = __float2bfloat16(vf.x - __bfloat162float(h0));
                __nv_bfloat16 l1 = __float2bfloat16(vf.y - __bfloat162float(h1));
                __nv_bfloat16 l2 = __float2bfloat16(vf.z - __bfloat162float(h2));
                __nv_bfloat16 l3 = __float2bfloat16(vf.w - __bfloat162float(h3));
                *(__nv_bfloat162*)&Vl[kj * SQP + d4 * 4]     = __nv_bfloat162(l0, l1);
                *(__nv_bfloat162*)&Vl[kj * SQP + d4 * 4 + 2] = __nv_bfloat162(l2, l3);
            }
        }
        const int4 mk4 = *(const int4*)(amask + b * SS + kb + c * 4);
        __syncthreads();   // staging visible

        // S = Qh*Kh + Qh*Kl + Ql*Kh (HMMA, warp tile 16x32)
        float acc4[4][4];
        #pragma unroll
        for (int nt = 0; nt < 4; nt++)
            #pragma unroll
            for (int e = 0; e < 4; e++) acc4[nt][e] = 0.0f;

        #pragma unroll
        for (int p = 0; p < 3; p++) {
            const uint32_t aB = sb + ((p == 2) ? A_QL : A_QH);
            const uint32_t bB = sb + ((p == 1) ? A_KL : A_KH);
            #pragma unroll
            for (int ks = 0; ks < 8; ks++) {
                const int k0 = ks * 16;
                uint32_t aF[4], bF[4][2];
                LDSM_X4(aF[0], aF[1], aF[2], aF[3],
                        aB + (uint32_t)((wm + lr) * (SQP * 2) + (k0 + 8 * hl) * 2));
                #pragma unroll
                for (int nt2 = 0; nt2 < 2; nt2++) {
                    uint32_t r0, r1, r2, r3;
                    LDSM_X4(r0, r1, r2, r3,
                            bB + (uint32_t)((wn + nt2 * 16 + lr) * (SQP * 2)
                                          + (k0 + 8 * hl) * 2));
                    bF[2 * nt2][0]     = r0;
                    bF[2 * nt2 + 1][0] = r1;
                    bF[2 * nt2][1]     = r2;
                    bF[2 * nt2 + 1][1] = r3;
                }
                #pragma unroll
                for (int nt = 0; nt < 4; nt++)
                    MMA16816(acc4[nt], aF, bF[nt]);
            }
        }

        // Store S transposed: PsT[key][query] (conflict-free scalar stores)
        {
            const int srow = wm + (lane >> 2);
            #pragma unroll
            for (int nt = 0; nt < 4; nt++) {
                const int scol = wn + nt * 8 + (lane & 3) * 2;
                PsT[scol * PP + srow]           = acc4[nt][0];
                PsT[(scol + 1) * PP + srow]     = acc4[nt][1];
                PsT[scol * PP + srow + 8]       = acc4[nt][2];
                PsT[(scol + 1) * PP + srow + 8] = acc4[nt][3];
            }
        }
        __syncthreads();   // S visible

        // Each thread reads its s[4][4] (qrows r*4.., kcols c*4..)
        float s[4][4];
        #pragma unroll
        for (int j = 0; j < 4; j++) {
            float4 v = *(const float4*)&PsT[(c * 4 + j) * PP + r * 4];
            s[0][j] = v.x; s[1][j] = v.y; s[2][j] = v.z; s[3][j] = v.w;
        }

        // Mask + online softmax
        const int mok[4] = {mk4.x, mk4.y, mk4.z, mk4.w};
        #pragma unroll
        for (int i = 0; i < 4; i++) {
            const int qi = q0 + r * 4 + i;
            #pragma unroll
            for (int j = 0; j < 4; j++) {
                const int kj = kb + c * 4 + j;
                bool ok = (kj <= qi) && (kj > qi - WINDOW) && (mok[j] > 0);
                if (!ok) s[i][j] = -FLT_MAX;
            }
            float mx = fmaxf(fmaxf(s[i][0], s[i][1]), fmaxf(s[i][2], s[i][3]));
            #pragma unroll
            for (int w = 1; w <= 8; w <<= 1)
                mx = fmaxf(mx, __shfl_xor_sync(0xffffffffu, mx, w));

            float mnew = fmaxf(m[i], mx);
            float scl = __expf(m[i] - mnew);
            m[i] = mnew;

            float sum = 0.0f;
            #pragma unroll
            for (int j = 0; j < 4; j++) {
                float p = (s[i][j] > -1e37f) ? __expf(s[i][j] - mnew) : 0.0f;
                s[i][j] = p;
                sum += p;
            }
            #pragma unroll
            for (int w = 1; w <= 8; w <<= 1)
                sum += __shfl_xor_sync(0xffffffffu, sum, w);

            l[i] = l[i] * scl + sum;
            if (c == 0) sc_s[r * 4 + i] = scl;   // publish per-row rescale
        }

        // Stage P as bf16 hi/lo, row-major [q][k] pitch 72
        #pragma unroll
        for (int i = 0; i < 4; i++) {
            const int prow = (r * 4 + i) * PQP + c * 4;
            #pragma unroll
            for (int j2 = 0; j2 < 2; j2++) {
                float x0 = s[i][2 * j2], x1 = s[i][2 * j2 + 1];
                __nv_bfloat16 h0 = __float2bfloat16(x0);
                __nv_bfloat16 h1 = __float2bfloat16(x1);
                *(__nv_bfloat162*)&Ph[prow + 2 * j2] = __nv_bfloat162(h0, h1);
                __nv_bfloat16 l0 = __float2bfloat16(x0 - __bfloat162float(h0));
                __nv_bfloat16 l1 = __float2bfloat16(x1 - __bfloat162float(h1));
                *(__nv_bfloat162*)&Pl[prow + 2 * j2] = __nv_bfloat162(l0, l1);
            }
        }
        __syncthreads();   // P + scl visible

        // Rescale O fragments, then O += Ph*Vh + Ph*Vl + Pl*Vh
        {
            const float s0 = sc_s[wm + (lane >> 2)];
            const float s1 = sc_s[wm + (lane >> 2) + 8];
            #pragma unroll
            for (int nt = 0; nt < 8; nt++) {
                acco[nt][0] *= s0; acco[nt][1] *= s0;
                acco[nt][2] *= s1; acco[nt][3] *= s1;
            }
        }
        #pragma unroll
        for (int p = 0; p < 3; p++) {
            const uint32_t aB = sb + ((p == 2) ? A_PL : A_PH);
            const uint32_t vB = sb + ((p == 1) ? A_VL : A_VH);
            #pragma unroll
            for (int ks = 0; ks < 4; ks++) {
                const int k0 = ks * 16;
                uint32_t aF[4], bF[8][2];
                LDSM_X4(aF[0], aF[1], aF[2], aF[3],
                        aB + (uint32_t)((wm + lr) * (PQP * 2) + (k0 + 8 * hl) * 2));
                #pragma unroll
                for (int dt = 0; dt < 4; dt++) {
                    uint32_t r0, r1, r2, r3;
                    uint32_t addr = vB + (uint32_t)((k0 + vkr) * (SQP * 2)
                                                  + (wn2 + dt * 16 + vdc) * 2);
                    LDSM_X4_T(r0, r1, r2, r3, addr);
                    bF[2 * dt][0]     = r0;   // d-tile even: k 0-7
                    bF[2 * dt][1]     = r1;   // d-tile even: k 8-15
                    bF[2 * dt + 1][0] = r2;   // d-tile odd:  k 0-7
                    bF[2 * dt + 1][1] = r3;   // d-tile odd:  k 8-15
                }
                #pragma unroll
                for (int nt = 0; nt < 8; nt++)
                    MMA16816(acco[nt], aF, bF[nt]);
            }
        }
    }

    // Publish 1/l per row, then fragment epilogue (tf32-rounded fp32)
    __syncthreads();
    if (c == 0) {
        #pragma unroll
        for (int i = 0; i < 4; i++)
            sc_s[r * 4 + i] = 1.0f / l[i];
    }
    __syncthreads();

    {
        const int erow = lane >> 2;
        const int ecol = (lane & 3) * 2;
        const float inv0 = sc_s[wm + erow];
        const float inv1 = sc_s[wm + erow + 8];
        const long base0 = ((long)(b * SS + q0 + wm + erow)) * DD + h * HDIM;
        const long base1 = base0 + 8L * DD;
        #pragma unroll
        for (int nt = 0; nt < 8; nt++) {
            const int col = wn2 + nt * 8 + ecol;
            *(float2*)(O + base0 + col) = make_float2(
                rna_tf32(acco[nt][0] * inv0), rna_tf32(acco[nt][1] * inv0));
            *(float2*)(O + base1 + col) = make_float2(
                rna_tf32(acco[nt][2] * inv1), rna_tf32(acco[nt][3] * inv1));
        }
    }
}

// ---------------------------------------------------------------------------
// Launch — QK bf16x3 gemm in slot 4 (profile target).
// ---------------------------------------------------------------------------
extern "C" void kernel_launch(void* const* d_in, const int* in_sizes, int n_in,
                              void* d_out, int out_size)
{
    const float* hs    = (const float*)d_in[0];
    const int*   amask = (const int*)  d_in[1];
    const float* Wq    = (const float*)d_in[2];
    const float* Wk    = (const float*)d_in[3];
    const float* Wv    = (const float*)d_in[4];
    const float* Wo    = (const float*)d_in[5];
    const float* bo    = (const float*)d_in[6];
    float*       out   = (float*)d_out;

    float *qkv, *ao, *wT;
    __nv_bfloat16 *ahi, *alo, *whi, *wlo;
    cudaGetSymbolAddress((void**)&qkv, g_qkv);
    cudaGetSymbolAddress((void**)&ao,  g_ao);
    cudaGetSymbolAddress((void**)&ahi, g_ahi);
    cudaGetSymbolAddress((void**)&alo, g_alo);
    cudaGetSymbolAddress((void**)&whi, g_whi);
    cudaGetSymbolAddress((void**)&wlo, g_wlo);
    cudaGetSymbolAddress((void**)&wT,  g_wT);

    cudaFuncSetAttribute(gemm_bf16x3_kernel,
                         cudaFuncAttributeMaxDynamicSharedMemorySize, GSMEM_TOTAL);
    cudaFuncSetAttribute(gemm_tf32_kernel,
                         cudaFuncAttributeMaxDynamicSharedMemorySize, TSMEM_TOTAL);
    cudaFuncSetAttribute(attn_local_kernel,
                         cudaFuncAttributeMaxDynamicSharedMemorySize, ATT_SMEM_BYTES);

    const int n4 = MROWS * DD / 4;

    // (1) hs -> bf16 hi/lo + tf32-rounded fp32 (in g_ao)
    split3_kernel<<<(n4 + 255) / 256, 256>>>(hs, ahi, alo, ao, n4);

    // (2) all weight prep in one launch
    dim3 wgrid(DD / 32, DD / 32, 4);
    wprep_kernel<<<wgrid, 256>>>(Wq, Wk, Wv, Wo, whi, wlo, wT);

    // (3) V GEMM (single-pass tf32)
    dim3 tgrid(DD / 128, MROWS / 128);
    gemm_tf32_kernel<<<tgrid, 256, TSMEM_TOTAL>>>(ao, wT, nullptr, qkv + 2 * MD);

    // (4) fused QK GEMM (bf16x3)  <-- ncu capture slot
    dim3 qkgrid(2 * DD / 128, MROWS / 128);
    gemm_bf16x3_kernel<<<qkgrid, 256, GSMEM_TOTAL>>>(ahi, alo, whi, wlo, nullptr, qkv);

    // (5) attention (HMMA S + HMMA PV): overwrites g_ao
    dim3 attn_grid(SS / BQ, HH, BB);
    attn_local_kernel<<<attn_grid, 256, ATT_SMEM_BYTES>>>(
        qkv, qkv + MD, qkv + 2 * MD, amask, ao);

    // (6) output projection (single-pass tf32)
    gemm_tf32_kernel<<<tgrid, 256, TSMEM_TOTAL>>>(ao, wT + (long)DD * DD, bo, out);
}

// round 17
// speedup vs baseline: 1.5407x; 1.5407x over previous
#include <cuda_runtime.h>
#include <cuda_bf16.h>
#include <float.h>
#include <stdint.h>

// Problem constants
#define BB     2
#define SS     2048
#define DD     2048
#define HH     16
#define HDIM   128
#define WINDOW 256
#define MROWS  (BB * SS)   // 4096
#define MD     ((long)MROWS * DD)

// ---------------------------------------------------------------------------
// Scratch (device globals — no allocation allowed)
// ---------------------------------------------------------------------------
__device__ float g_qkv[3 * MROWS * DD];       // q | k | v
__device__ float g_ao [MROWS * DD];           // rna(hs) first, then attn output
__device__ __nv_bfloat16 g_ahi[MROWS * DD];
__device__ __nv_bfloat16 g_alo[MROWS * DD];
__device__ __nv_bfloat16 g_whi[2 * DD * DD];  // Wq | Wk  (bf16 hi)
__device__ __nv_bfloat16 g_wlo[2 * DD * DD];  // Wq | Wk  (bf16 lo)
__device__ float g_wT[2 * DD * DD];           // WvT | WoT (tf32-rounded fp32)

// ---------------------------------------------------------------------------
// PTX helpers (family-wide only: harness emits compute_103 PTX -> no tcgen05)
// ---------------------------------------------------------------------------
__device__ __forceinline__ uint32_t smem_u32(const void* p) {
    uint32_t a;
    asm("{ .reg .u64 t; cvta.to.shared.u64 t, %1; cvt.u32.u64 %0, t; }"
        : "=r"(a) : "l"(p));
    return a;
}

__device__ __forceinline__ float rna_tf32(float x) {
    float y;
    asm("cvt.rna.tf32.f32 %0, %1;" : "=f"(y) : "f"(x));
    return y;
}

#define CP16(dst, src) \
    asm volatile("cp.async.cg.shared.global [%0], [%1], 16;" :: "r"(dst), "l"(src))
#define CP_COMMIT() asm volatile("cp.async.commit_group;" ::: "memory")
#define CP_WAIT1()  asm volatile("cp.async.wait_group 1;" ::: "memory")

#define LDSM_X4(r0, r1, r2, r3, addr) \
    asm volatile("ldmatrix.sync.aligned.m8n8.x4.shared.b16 {%0,%1,%2,%3}, [%4];" \
        : "=r"(r0), "=r"(r1), "=r"(r2), "=r"(r3) : "r"(addr))

#define LDSM_X4_T(r0, r1, r2, r3, addr) \
    asm volatile("ldmatrix.sync.aligned.m8n8.x4.trans.shared.b16 {%0,%1,%2,%3}, [%4];" \
        : "=r"(r0), "=r"(r1), "=r"(r2), "=r"(r3) : "r"(addr))

#define MMA16816(d, a, b) \
    asm volatile("mma.sync.aligned.m16n8k16.row.col.f32.bf16.bf16.f32 " \
        "{%0,%1,%2,%3}, {%4,%5,%6,%7}, {%8,%9}, {%0,%1,%2,%3};" \
        : "+f"((d)[0]), "+f"((d)[1]), "+f"((d)[2]), "+f"((d)[3]) \
        : "r"((a)[0]), "r"((a)[1]), "r"((a)[2]), "r"((a)[3]), \
          "r"((b)[0]), "r"((b)[1]))

#define MMA_TF32(d, a, b) \
    asm volatile("mma.sync.aligned.m16n8k8.row.col.f32.tf32.tf32.f32 " \
        "{%0,%1,%2,%3}, {%4,%5,%6,%7}, {%8,%9}, {%0,%1,%2,%3};" \
        : "+f"((d)[0]), "+f"((d)[1]), "+f"((d)[2]), "+f"((d)[3]) \
        : "r"((a)[0]), "r"((a)[1]), "r"((a)[2]), "r"((a)[3]), \
          "r"((b)[0]), "r"((b)[1]))

// ---------------------------------------------------------------------------
// Split fp32 -> bf16 hi + lo AND tf32-rounded fp32 copy (for the tf32 V gemm)
// ---------------------------------------------------------------------------
__global__ __launch_bounds__(256) void split3_kernel(
    const float* __restrict__ X, __nv_bfloat16* __restrict__ H,
    __nv_bfloat16* __restrict__ L, float* __restrict__ R, int n4)
{
    int i = blockIdx.x * blockDim.x + threadIdx.x;
    if (i >= n4) return;
    float4 x = ((const float4*)X)[i];
    __nv_bfloat16 h0 = __float2bfloat16(x.x);
    __nv_bfloat16 h1 = __float2bfloat16(x.y);
    __nv_bfloat16 h2 = __float2bfloat16(x.z);
    __nv_bfloat16 h3 = __float2bfloat16(x.w);
    __nv_bfloat16 l0 = __float2bfloat16(x.x - __bfloat162float(h0));
    __nv_bfloat16 l1 = __float2bfloat16(x.y - __bfloat162float(h1));
    __nv_bfloat16 l2 = __float2bfloat16(x.z - __bfloat162float(h2));
    __nv_bfloat16 l3 = __float2bfloat16(x.w - __bfloat162float(h3));
    ((__nv_bfloat162*)H)[2*i]   = __nv_bfloat162(h0, h1);
    ((__nv_bfloat162*)H)[2*i+1] = __nv_bfloat162(h2, h3);
    ((__nv_bfloat162*)L)[2*i]   = __nv_bfloat162(l0, l1);
    ((__nv_bfloat162*)L)[2*i+1] = __nv_bfloat162(l2, l3);
    float4 r = make_float4(rna_tf32(x.x), rna_tf32(x.y),
                           rna_tf32(x.z), rna_tf32(x.w));
    ((float4*)R)[i] = r;
}

// ---------------------------------------------------------------------------
// Weight prep, one launch: z 0..1 -> bf16 transposed split of Wq/Wk;
// z 2..3 -> tf32-rounded transpose of Wv/Wo.
// ---------------------------------------------------------------------------
__global__ __launch_bounds__(256) void wprep_kernel(
    const float* __restrict__ Wq, const float* __restrict__ Wk,
    const float* __restrict__ Wv, const float* __restrict__ Wo,
    __nv_bfloat16* __restrict__ TH, __nv_bfloat16* __restrict__ TL,
    float* __restrict__ T32)
{
    __shared__ float t[32][33];
    const int z = blockIdx.z;
    const float* W = (z == 0) ? Wq : (z == 1) ? Wk : (z == 2) ? Wv : Wo;
    const int n0 = blockIdx.x * 32, k0 = blockIdx.y * 32;
    const int tx = threadIdx.x & 31, ty = threadIdx.x >> 5;
    #pragma unroll
    for (int i = 0; i < 32; i += 8)
        t[ty + i][tx] = W[(long)(k0 + ty + i) * DD + n0 + tx];
    __syncthreads();
    if (z < 2) {
        __nv_bfloat16* th = TH + (long)z * DD * DD;
        __nv_bfloat16* tl = TL + (long)z * DD * DD;
        #pragma unroll
        for (int i = 0; i < 32; i += 8) {
            float x = t[tx][ty + i];
            long o = (long)(n0 + ty + i) * DD + k0 + tx;
            __nv_bfloat16 h = __float2bfloat16(x);
            th[o] = h;
            tl[o] = __float2bfloat16(x - __bfloat162float(h));
        }
    } else {
        float* out = T32 + (long)(z - 2) * DD * DD;
        #pragma unroll
        for (int i = 0; i < 32; i += 8)
            out[(long)(n0 + ty + i) * DD + k0 + tx] = rna_tf32(t[tx][ty + i]);
    }
}

// ---------------------------------------------------------------------------
// bf16x3 HMMA GEMM, packed-N weights (verified: 3-stage, 2 CTAs/SM).
// ---------------------------------------------------------------------------
#define GKB      64
#define GNIT     96
#define GPAD     72
#define G_OPB    (128 * GPAD * 2)
#define G_STAGEB (2 * G_OPB)
#define GSMEM_TOTAL (3 * G_STAGEB)        // 110592 B

__device__ __forceinline__ void g_load_stage(
    uint32_t sbase, int stage, int tid,
    const __nv_bfloat16* __restrict__ Asrc, const __nv_bfloat16* __restrict__ Bsrc,
    long row0, long bcol0, int kc)
{
    const uint32_t abase = sbase + stage * G_STAGEB;
    const uint32_t bbase = abase + G_OPB;
    const __nv_bfloat16* Ap = Asrc + row0 * DD + kc;
    const __nv_bfloat16* Bp = Bsrc + bcol0 * DD + kc;
    #pragma unroll
    for (int i = 0; i < 4; i++) {
        int idx = i * 256 + tid;
        int r  = idx >> 3;
        int ch = idx & 7;
        uint32_t so = (uint32_t)(r * (GPAD * 2) + ch * 16);
        CP16(abase + so, Ap + (long)r * DD + ch * 8);
        CP16(bbase + so, Bp + (long)r * DD + ch * 8);
    }
}

__global__ __launch_bounds__(256, 2) void gemm_bf16x3_kernel(
    const __nv_bfloat16* __restrict__ Ahi, const __nv_bfloat16* __restrict__ Alo,
    const __nv_bfloat16* __restrict__ Bhi, const __nv_bfloat16* __restrict__ Blo,
    const float* __restrict__ bias, float* __restrict__ Cbase)
{
    extern __shared__ char gsm[];
    const uint32_t sb = smem_u32(gsm);
    const int tid  = threadIdx.x;
    const int wid  = tid >> 5;
    const int lane = tid & 31;
    const long bcol0 = (long)blockIdx.x * 128;
    const long row0  = (long)blockIdx.y * 128;
    const int  which = (int)(bcol0 >> 11);           // 0..1 (Q,K)
    const long cc0   = bcol0 & 2047;
    float* C = Cbase + (long)which * MD;

    const int warp_m = (wid >> 1) * 32;
    const int warp_n = (wid & 1) * 64;
    const int lr = lane & 15;
    const int hl = lane >> 4;

    float acc[2][8][4];
    #pragma unroll
    for (int mt = 0; mt < 2; mt++)
        #pragma unroll
        for (int nt = 0; nt < 8; nt++)
            #pragma unroll
            for (int e = 0; e < 4; e++)
                acc[mt][nt][e] = 0.0f;

    g_load_stage(sb, 0, tid, Ahi, Bhi, row0, bcol0, 0);
    CP_COMMIT();
    g_load_stage(sb, 1, tid, Ahi, Bhi, row0, bcol0, GKB);
    CP_COMMIT();

    int s = 0, ps = 2;
    #pragma unroll 1
    for (int it = 0; it < GNIT; it++) {
        CP_WAIT1();
        __syncthreads();

        const int nit = it + 2;
        if (nit < GNIT) {
            const int pass = nit >> 5;
            const int kc = (nit & 31) * GKB;
            const __nv_bfloat16* As = (pass == 2) ? Alo : Ahi;
            const __nv_bfloat16* Bs = (pass == 1) ? Blo : Bhi;
            g_load_stage(sb, ps, tid, As, Bs, row0, bcol0, kc);
        }
        CP_COMMIT();

        const uint32_t sA = sb + s * G_STAGEB;
        const uint32_t sB = sA + G_OPB;
        #pragma unroll
        for (int ks = 0; ks < 4; ks++) {
            const int k0 = ks * 16;
            uint32_t aF[2][4], bF[8][2];
            #pragma unroll
            for (int mt = 0; mt < 2; mt++) {
                uint32_t addr = sA + (uint32_t)((warp_m + mt * 16 + lr) * (GPAD * 2)
                                              + (k0 + 8 * hl) * 2);
                LDSM_X4(aF[mt][0], aF[mt][1], aF[mt][2], aF[mt][3], addr);
            }
            #pragma unroll
            for (int nt2 = 0; nt2 < 4; nt2++) {
                uint32_t r0, r1, r2, r3;
                uint32_t addr = sB + (uint32_t)((warp_n + nt2 * 16 + lr) * (GPAD * 2)
                                              + (k0 + 8 * hl) * 2);
                LDSM_X4(r0, r1, r2, r3, addr);
                bF[2 * nt2][0]     = r0;
                bF[2 * nt2 + 1][0] = r1;
                bF[2 * nt2][1]     = r2;
                bF[2 * nt2 + 1][1] = r3;
            }
            #pragma unroll
            for (int mt = 0; mt < 2; mt++)
                #pragma unroll
                for (int nt = 0; nt < 8; nt++)
                    MMA16816(acc[mt][nt], aF[mt], bF[nt]);
        }
        s = (s == 2) ? 0 : s + 1;
        ps = (ps == 2) ? 0 : ps + 1;
    }

    const int erow = lane >> 2;
    const int ecol = (lane & 3) * 2;
    #pragma unroll
    for (int mt = 0; mt < 2; mt++) {
        #pragma unroll
        for (int nt = 0; nt < 8; nt++) {
            const long r  = row0 + warp_m + mt * 16 + erow;
            const long cc = cc0 + warp_n + nt * 8 + ecol;
            float b0 = bias ? bias[cc] : 0.0f;
            float b1 = bias ? bias[cc + 1] : 0.0f;
            float2 v0 = make_float2(acc[mt][nt][0] + b0, acc[mt][nt][1] + b1);
            float2 v1 = make_float2(acc[mt][nt][2] + b0, acc[mt][nt][3] + b1);
            *(float2*)(C + r * DD + cc)       = v0;
            *(float2*)(C + (r + 8) * DD + cc) = v1;
        }
    }
}

// ---------------------------------------------------------------------------
// Single-pass TF32 GEMM with ldmatrix fragments (verified round 10).
// ---------------------------------------------------------------------------
#define TKB   32
#define TNIT  64
#define TPAD  36
#define T_OPB (128 * TPAD * 4)
#define T_STAGEB (2 * T_OPB)
#define TSMEM_TOTAL (3 * T_STAGEB)        // 110592 B

__device__ __forceinline__ void t_load_stage(
    uint32_t sbase, int stage, int tid,
    const float* __restrict__ Asrc, const float* __restrict__ Bsrc,
    long row0, long col0, int kc)
{
    const uint32_t abase = sbase + stage * T_STAGEB;
    const uint32_t bbase = abase + T_OPB;
    const float* Ap = Asrc + row0 * DD + kc;
    const float* Bp = Bsrc + col0 * DD + kc;
    #pragma unroll
    for (int i = 0; i < 4; i++) {
        int idx = i * 256 + tid;
        int r  = idx >> 3;
        int ch = idx & 7;
        uint32_t so = (uint32_t)(r * (TPAD * 4) + ch * 16);
        CP16(abase + so, Ap + (long)r * DD + ch * 4);
        CP16(bbase + so, Bp + (long)r * DD + ch * 4);
    }
}

__global__ __launch_bounds__(256, 2) void gemm_tf32_kernel(
    const float* __restrict__ A, const float* __restrict__ Bt,
    const float* __restrict__ bias, float* __restrict__ C)
{
    extern __shared__ char tsm[];
    const uint32_t sb = smem_u32(tsm);
    const int tid  = threadIdx.x;
    const int wid  = tid >> 5;
    const int lane = tid & 31;
    const long col0 = (long)blockIdx.x * 128;
    const long row0 = (long)blockIdx.y * 128;

    const int warp_m = (wid >> 1) * 32;
    const int warp_n = (wid & 1) * 64;

    const int a_row = lane & 15;
    const int a_kof = (lane >> 4) * 4;
    const int b_row = (lane & 7) + ((lane >> 4) << 3);
    const int b_kof = ((lane >> 3) & 1) * 4;

    float acc[2][8][4];
    #pragma unroll
    for (int mt = 0; mt < 2; mt++)
        #pragma unroll
        for (int nt = 0; nt < 8; nt++)
            #pragma unroll
            for (int e = 0; e < 4; e++)
                acc[mt][nt][e] = 0.0f;

    t_load_stage(sb, 0, tid, A, Bt, row0, col0, 0);
    CP_COMMIT();
    t_load_stage(sb, 1, tid, A, Bt, row0, col0, TKB);
    CP_COMMIT();

    int s = 0, ps = 2;
    #pragma unroll 1
    for (int it = 0; it < TNIT; it++) {
        CP_WAIT1();
        __syncthreads();

        const int nit = it + 2;
        if (nit < TNIT)
            t_load_stage(sb, ps, tid, A, Bt, row0, col0, nit * TKB);
        CP_COMMIT();

        const uint32_t sA = sb + s * T_STAGEB;
        const uint32_t sB = sA + T_OPB;
        #pragma unroll
        for (int ks = 0; ks < 4; ks++) {
            const int k0 = ks * 8;
            uint32_t aF[2][4], bF[8][2];
            #pragma unroll
            for (int mt = 0; mt < 2; mt++) {
                uint32_t addr = sA + (uint32_t)((warp_m + mt * 16 + a_row) * (TPAD * 4)
                                              + (k0 + a_kof) * 4);
                LDSM_X4(aF[mt][0], aF[mt][1], aF[mt][2], aF[mt][3], addr);
            }
            #pragma unroll
            for (int nt2 = 0; nt2 < 4; nt2++) {
                uint32_t r0, r1, r2, r3;
                uint32_t addr = sB + (uint32_t)((warp_n + nt2 * 16 + b_row) * (TPAD * 4)
                                              + (k0 + b_kof) * 4);
                LDSM_X4(r0, r1, r2, r3, addr);
                bF[2 * nt2][0]     = r0;
                bF[2 * nt2][1]     = r1;
                bF[2 * nt2 + 1][0] = r2;
                bF[2 * nt2 + 1][1] = r3;
            }
            #pragma unroll
            for (int mt = 0; mt < 2; mt++)
                #pragma unroll
                for (int nt = 0; nt < 8; nt++)
                    MMA_TF32(acc[mt][nt], aF[mt], bF[nt]);
        }
        s = (s == 2) ? 0 : s + 1;
        ps = (ps == 2) ? 0 : ps + 1;
    }

    const int erow = lane >> 2;
    const int ecol = (lane & 3) * 2;
    #pragma unroll
    for (int mt = 0; mt < 2; mt++) {
        #pragma unroll
        for (int nt = 0; nt < 8; nt++) {
            const long r  = row0 + warp_m + mt * 16 + erow;
            const long cc = col0 + warp_n + nt * 8 + ecol;
            float b0 = bias ? bias[cc] : 0.0f;
            float b1 = bias ? bias[cc + 1] : 0.0f;
            float2 v0 = make_float2(acc[mt][nt][0] + b0, acc[mt][nt][1] + b1);
            float2 v1 = make_float2(acc[mt][nt][2] + b0, acc[mt][nt][3] + b1);
            *(float2*)(C + r * DD + cc)       = v0;
            *(float2*)(C + (r + 8) * DD + cc) = v1;
        }
    }
}

// ---------------------------------------------------------------------------
// Local-window attention — fully tensorized (verified round 16: correct at
// rel_err 4.162e-4; round-16 wall time was a degraded-clock run — the
// byte-identical QK gemm ran 1.56x slower with identical pipe utilization).
//   S = Qh*Kh + Qh*Kl + Ql*Kh   (HMMA)
//   O = Ph*Vh + Ph*Vl + Pl*Vh   (HMMA, V via ldmatrix.trans)
// ---------------------------------------------------------------------------
#define BQ   64
#define BKC  64
#define SQP  136                           // Q/K/V bf16 row pitch (272 B)
#define PQP  72                            // P bf16 row pitch (144 B)
#define PP   68                            // PsT pitch in floats (272 B)
#define A_QH 0
#define A_QL (A_QH + 64 * SQP * 2)         // 17408
#define A_KH (A_QL + 64 * SQP * 2)         // 34816
#define A_KL (A_KH + 64 * SQP * 2)         // 52224
#define A_VH (A_KL + 64 * SQP * 2)         // 69632
#define A_VL (A_VH + 64 * SQP * 2)         // 87040
#define A_PH (A_VL + 64 * SQP * 2)         // 104448
#define A_PL (A_PH + 64 * PQP * 2)         // 113664
#define A_PS (A_PL + 64 * PQP * 2)         // 122880
#define A_SC (A_PS + 64 * PP * 4)          // 140288 (64 floats scl / linv)
#define ATT_SMEM_BYTES (A_SC + 64 * 4)     // 140544

__global__ __launch_bounds__(256, 1) void attn_local_kernel(
    const float* __restrict__ Q, const float* __restrict__ K,
    const float* __restrict__ V, const int* __restrict__ amask,
    float* __restrict__ O)
{
    const int q0 = blockIdx.x * BQ;
    const int h  = blockIdx.y;
    const int b  = blockIdx.z;

    extern __shared__ char asmem[];
    const uint32_t sb = smem_u32(asmem);
    __nv_bfloat16* Qh = (__nv_bfloat16*)(asmem + A_QH);
    __nv_bfloat16* Ql = (__nv_bfloat16*)(asmem + A_QL);
    __nv_bfloat16* Kh = (__nv_bfloat16*)(asmem + A_KH);
    __nv_bfloat16* Kl = (__nv_bfloat16*)(asmem + A_KL);
    __nv_bfloat16* Vh = (__nv_bfloat16*)(asmem + A_VH);
    __nv_bfloat16* Vl = (__nv_bfloat16*)(asmem + A_VL);
    __nv_bfloat16* Ph = (__nv_bfloat16*)(asmem + A_PH);
    __nv_bfloat16* Pl = (__nv_bfloat16*)(asmem + A_PL);
    float* PsT  = (float*)(asmem + A_PS);
    float* sc_s = (float*)(asmem + A_SC);

    const int tid  = threadIdx.x;
    const int wid  = tid >> 5;
    const int lane = tid & 31;
    const int r    = tid >> 4;             // softmax mapping (q rows r*4+i)
    const int c    = tid & 15;             // key cols c*4+j
    const int wm   = (wid & 3) * 16;       // S/PV warp tile rows (q)
    const int wn   = (wid >> 2) * 32;      // S warp tile cols (k)
    const int wn2  = (wid >> 2) * 64;      // PV warp tile cols (d)
    const int lr   = lane & 15;
    const int hl   = lane >> 4;
    const int vkr  = (lane & 7) + ((lane >> 3) & 1) * 8;   // trans-LDSM k row
    const int vdc  = (lane >> 4) * 8;                      // trans-LDSM d col

    // Q staging: fp32 -> bf16 hi/lo, pitch 136
    const float* qbase = Q + ((long)(b * SS + q0)) * DD + h * HDIM;
    #pragma unroll
    for (int e = tid; e < BQ * (HDIM / 4); e += 256) {
        int qi = e >> 5, d4 = e & 31;
        float4 f = *(const float4*)(qbase + (long)qi * DD + d4 * 4);
        __nv_bfloat16 h0 = __float2bfloat16(f.x), h1 = __float2bfloat16(f.y);
        __nv_bfloat16 h2 = __float2bfloat16(f.z), h3 = __float2bfloat16(f.w);
        *(__nv_bfloat162*)&Qh[qi * SQP + d4 * 4]     = __nv_bfloat162(h0, h1);
        *(__nv_bfloat162*)&Qh[qi * SQP + d4 * 4 + 2] = __nv_bfloat162(h2, h3);
        __nv_bfloat16 l0 = __float2bfloat16(f.x - __bfloat162float(h0));
        __nv_bfloat16 l1 = __float2bfloat16(f.y - __bfloat162float(h1));
        __nv_bfloat16 l2 = __float2bfloat16(f.z - __bfloat162float(h2));
        __nv_bfloat16 l3 = __float2bfloat16(f.w - __bfloat162float(h3));
        *(__nv_bfloat162*)&Ql[qi * SQP + d4 * 4]     = __nv_bfloat162(l0, l1);
        *(__nv_bfloat162*)&Ql[qi * SQP + d4 * 4 + 2] = __nv_bfloat162(l2, l3);
    }

    float m[4], l[4];
    float acco[8][4];                      // O fragments: warp tile 16 x 64
    #pragma unroll
    for (int i = 0; i < 4; i++) { m[i] = -FLT_MAX; l[i] = 0.0f; }
    #pragma unroll
    for (int nt = 0; nt < 8; nt++)
        #pragma unroll
        for (int e = 0; e < 4; e++) acco[nt][e] = 0.0f;

    for (int t = 0; t < 5; t++) {
        const int kb = q0 - WINDOW + t * BKC;
        if (kb < 0) continue;

        __syncthreads();   // prev chunk's MMAs done with K/V/P buffers

        const float* kbase = K + ((long)(b * SS + kb)) * DD + h * HDIM;
        const float* vbase = V + ((long)(b * SS + kb)) * DD + h * HDIM;
        #pragma unroll
        for (int e = tid; e < BKC * (HDIM / 4); e += 256) {
            int kj = e >> 5, d4 = e & 31;
            float4 kf = *(const float4*)(kbase + (long)kj * DD + d4 * 4);
            float4 vf = *(const float4*)(vbase + (long)kj * DD + d4 * 4);
            {
                __nv_bfloat16 h0 = __float2bfloat16(kf.x), h1 = __float2bfloat16(kf.y);
                __nv_bfloat16 h2 = __float2bfloat16(kf.z), h3 = __float2bfloat16(kf.w);
                *(__nv_bfloat162*)&Kh[kj * SQP + d4 * 4]     = __nv_bfloat162(h0, h1);
                *(__nv_bfloat162*)&Kh[kj * SQP + d4 * 4 + 2] = __nv_bfloat162(h2, h3);
                __nv_bfloat16 l0 = __float2bfloat16(kf.x - __bfloat162float(h0));
                __nv_bfloat16 l1 = __float2bfloat16(kf.y - __bfloat162float(h1));
                __nv_bfloat16 l2 = __float2bfloat16(kf.z - __bfloat162float(h2));
                __nv_bfloat16 l3 = __float2bfloat16(kf.w - __bfloat162float(h3));
                *(__nv_bfloat162*)&Kl[kj * SQP + d4 * 4]     = __nv_bfloat162(l0, l1);
                *(__nv_bfloat162*)&Kl[kj * SQP + d4 * 4 + 2] = __nv_bfloat162(l2, l3);
            }
            {
                __nv_bfloat16 h0 = __float2bfloat16(vf.x), h1 = __float2bfloat16(vf.y);
                __nv_bfloat16 h2 = __float2bfloat16(vf.z), h3 = __float2bfloat16(vf.w);
                *(__nv_bfloat162*)&Vh[kj * SQP + d4 * 4]     = __nv_bfloat162(h0, h1);
                *(__nv_bfloat162*)&Vh[kj * SQP + d4 * 4 + 2] = __nv_bfloat162(h2, h3);
                __nv_bfloat16 l0 = __float2bfloat16(vf.x - __bfloat162float(h0));
                __nv_bfloat16 l1 = __float2bfloat16(vf.y - __bfloat162float(h1));
                __nv_bfloat16 l2 = __float2bfloat16(vf.z - __bfloat162float(h2));
                __nv_bfloat16 l3 = __float2bfloat16(vf.w - __bfloat162float(h3));
                *(__nv_bfloat162*)&Vl[kj * SQP + d4 * 4]     = __nv_bfloat162(l0, l1);
                *(__nv_bfloat162*)&Vl[kj * SQP + d4 * 4 + 2] = __nv_bfloat162(l2, l3);
            }
        }
        const int4 mk4 = *(const int4*)(amask + b * SS + kb + c * 4);
        __syncthreads();   // staging visible

        // S = Qh*Kh + Qh*Kl + Ql*Kh (HMMA, warp tile 16x32)
        float acc4[4][4];
        #pragma unroll
        for (int nt = 0; nt < 4; nt++)
            #pragma unroll
            for (int e = 0; e < 4; e++) acc4[nt][e] = 0.0f;

        #pragma unroll
        for (int p = 0; p < 3; p++) {
            const uint32_t aB = sb + ((p == 2) ? A_QL : A_QH);
            const uint32_t bB = sb + ((p == 1) ? A_KL : A_KH);
            #pragma unroll
            for (int ks = 0; ks < 8; ks++) {
                const int k0 = ks * 16;
                uint32_t aF[4], bF[4][2];
                LDSM_X4(aF[0], aF[1], aF[2], aF[3],
                        aB + (uint32_t)((wm + lr) * (SQP * 2) + (k0 + 8 * hl) * 2));
                #pragma unroll
                for (int nt2 = 0; nt2 < 2; nt2++) {
                    uint32_t r0, r1, r2, r3;
                    LDSM_X4(r0, r1, r2, r3,
                            bB + (uint32_t)((wn + nt2 * 16 + lr) * (SQP * 2)
                                          + (k0 + 8 * hl) * 2));
                    bF[2 * nt2][0]     = r0;
                    bF[2 * nt2 + 1][0] = r1;
                    bF[2 * nt2][1]     = r2;
                    bF[2 * nt2 + 1][1] = r3;
                }
                #pragma unroll
                for (int nt = 0; nt < 4; nt++)
                    MMA16816(acc4[nt], aF, bF[nt]);
            }
        }

        // Store S transposed: PsT[key][query] (conflict-free scalar stores)
        {
            const int srow = wm + (lane >> 2);
            #pragma unroll
            for (int nt = 0; nt < 4; nt++) {
                const int scol = wn + nt * 8 + (lane & 3) * 2;
                PsT[scol * PP + srow]           = acc4[nt][0];
                PsT[(scol + 1) * PP + srow]     = acc4[nt][1];
                PsT[scol * PP + srow + 8]       = acc4[nt][2];
                PsT[(scol + 1) * PP + srow + 8] = acc4[nt][3];
            }
        }
        __syncthreads();   // S visible

        float s[4][4];
        #pragma unroll
        for (int j = 0; j < 4; j++) {
            float4 v = *(const float4*)&PsT[(c * 4 + j) * PP + r * 4];
            s[0][j] = v.x; s[1][j] = v.y; s[2][j] = v.z; s[3][j] = v.w;
        }

        // Mask + online softmax
        const int mok[4] = {mk4.x, mk4.y, mk4.z, mk4.w};
        #pragma unroll
        for (int i = 0; i < 4; i++) {
            const int qi = q0 + r * 4 + i;
            #pragma unroll
            for (int j = 0; j < 4; j++) {
                const int kj = kb + c * 4 + j;
                bool ok = (kj <= qi) && (kj > qi - WINDOW) && (mok[j] > 0);
                if (!ok) s[i][j] = -FLT_MAX;
            }
            float mx = fmaxf(fmaxf(s[i][0], s[i][1]), fmaxf(s[i][2], s[i][3]));
            #pragma unroll
            for (int w = 1; w <= 8; w <<= 1)
                mx = fmaxf(mx, __shfl_xor_sync(0xffffffffu, mx, w));

            float mnew = fmaxf(m[i], mx);
            float scl = __expf(m[i] - mnew);
            m[i] = mnew;

            float sum = 0.0f;
            #pragma unroll
            for (int j = 0; j < 4; j++) {
                float p = (s[i][j] > -1e37f) ? __expf(s[i][j] - mnew) : 0.0f;
                s[i][j] = p;
                sum += p;
            }
            #pragma unroll
            for (int w = 1; w <= 8; w <<= 1)
                sum += __shfl_xor_sync(0xffffffffu, sum, w);

            l[i] = l[i] * scl + sum;
            if (c == 0) sc_s[r * 4 + i] = scl;   // publish per-row rescale
        }

        // Stage P as bf16 hi/lo, row-major [q][k] pitch 72
        #pragma unroll
        for (int i = 0; i < 4; i++) {
            const int prow = (r * 4 + i) * PQP + c * 4;
            #pragma unroll
            for (int j2 = 0; j2 < 2; j2++) {
                float x0 = s[i][2 * j2], x1 = s[i][2 * j2 + 1];
                __nv_bfloat16 h0 = __float2bfloat16(x0);
                __nv_bfloat16 h1 = __float2bfloat16(x1);
                *(__nv_bfloat162*)&Ph[prow + 2 * j2] = __nv_bfloat162(h0, h1);
                __nv_bfloat16 l0 = __float2bfloat16(x0 - __bfloat162float(h0));
                __nv_bfloat16 l1 = __float2bfloat16(x1 - __bfloat162float(h1));
                *(__nv_bfloat162*)&Pl[prow + 2 * j2] = __nv_bfloat162(l0, l1);
            }
        }
        __syncthreads();   // P + scl visible

        // Rescale O fragments, then O += Ph*Vh + Ph*Vl + Pl*Vh
        {
            const float s0 = sc_s[wm + (lane >> 2)];
            const float s1 = sc_s[wm + (lane >> 2) + 8];
            #pragma unroll
            for (int nt = 0; nt < 8; nt++) {
                acco[nt][0] *= s0; acco[nt][1] *= s0;
                acco[nt][2] *= s1; acco[nt][3] *= s1;
            }
        }
        #pragma unroll
        for (int p = 0; p < 3; p++) {
            const uint32_t aB = sb + ((p == 2) ? A_PL : A_PH);
            const uint32_t vB = sb + ((p == 1) ? A_VL : A_VH);
            #pragma unroll
            for (int ks = 0; ks < 4; ks++) {
                const int k0 = ks * 16;
                uint32_t aF[4], bF[8][2];
                LDSM_X4(aF[0], aF[1], aF[2], aF[3],
                        aB + (uint32_t)((wm + lr) * (PQP * 2) + (k0 + 8 * hl) * 2));
                #pragma unroll
                for (int dt = 0; dt < 4; dt++) {
                    uint32_t r0, r1, r2, r3;
                    uint32_t addr = vB + (uint32_t)((k0 + vkr) * (SQP * 2)
                                                  + (wn2 + dt * 16 + vdc) * 2);
                    LDSM_X4_T(r0, r1, r2, r3, addr);
                    bF[2 * dt][0]     = r0;
                    bF[2 * dt][1]     = r1;
                    bF[2 * dt + 1][0] = r2;
                    bF[2 * dt + 1][1] = r3;
                }
                #pragma unroll
                for (int nt = 0; nt < 8; nt++)
                    MMA16816(acco[nt], aF, bF[nt]);
            }
        }
    }

    // Publish 1/l per row, then fragment epilogue (tf32-rounded fp32)
    __syncthreads();
    if (c == 0) {
        #pragma unroll
        for (int i = 0; i < 4; i++)
            sc_s[r * 4 + i] = 1.0f / l[i];
    }
    __syncthreads();

    {
        const int erow = lane >> 2;
        const int ecol = (lane & 3) * 2;
        const float inv0 = sc_s[wm + erow];
        const float inv1 = sc_s[wm + erow + 8];
        const long base0 = ((long)(b * SS + q0 + wm + erow)) * DD + h * HDIM;
        const long base1 = base0 + 8L * DD;
        #pragma unroll
        for (int nt = 0; nt < 8; nt++) {
            const int col = wn2 + nt * 8 + ecol;
            *(float2*)(O + base0 + col) = make_float2(
                rna_tf32(acco[nt][0] * inv0), rna_tf32(acco[nt][1] * inv0));
            *(float2*)(O + base1 + col) = make_float2(
                rna_tf32(acco[nt][2] * inv1), rna_tf32(acco[nt][3] * inv1));
        }
    }
}

// ---------------------------------------------------------------------------
// Launch — QK bf16x3 gemm in slot 4 (profile target / in-run clock control).
// ---------------------------------------------------------------------------
extern "C" void kernel_launch(void* const* d_in, const int* in_sizes, int n_in,
                              void* d_out, int out_size)
{
    const float* hs    = (const float*)d_in[0];
    const int*   amask = (const int*)  d_in[1];
    const float* Wq    = (const float*)d_in[2];
    const float* Wk    = (const float*)d_in[3];
    const float* Wv    = (const float*)d_in[4];
    const float* Wo    = (const float*)d_in[5];
    const float* bo    = (const float*)d_in[6];
    float*       out   = (float*)d_out;

    float *qkv, *ao, *wT;
    __nv_bfloat16 *ahi, *alo, *whi, *wlo;
    cudaGetSymbolAddress((void**)&qkv, g_qkv);
    cudaGetSymbolAddress((void**)&ao,  g_ao);
    cudaGetSymbolAddress((void**)&ahi, g_ahi);
    cudaGetSymbolAddress((void**)&alo, g_alo);
    cudaGetSymbolAddress((void**)&whi, g_whi);
    cudaGetSymbolAddress((void**)&wlo, g_wlo);
    cudaGetSymbolAddress((void**)&wT,  g_wT);

    cudaFuncSetAttribute(gemm_bf16x3_kernel,
                         cudaFuncAttributeMaxDynamicSharedMemorySize, GSMEM_TOTAL);
    cudaFuncSetAttribute(gemm_tf32_kernel,
                         cudaFuncAttributeMaxDynamicSharedMemorySize, TSMEM_TOTAL);
    cudaFuncSetAttribute(attn_local_kernel,
                         cudaFuncAttributeMaxDynamicSharedMemorySize, ATT_SMEM_BYTES);

    const int n4 = MROWS * DD / 4;

    // (1) hs -> bf16 hi/lo + tf32-rounded fp32 (in g_ao)
    split3_kernel<<<(n4 + 255) / 256, 256>>>(hs, ahi, alo, ao, n4);

    // (2) all weight prep in one launch
    dim3 wgrid(DD / 32, DD / 32, 4);
    wprep_kernel<<<wgrid, 256>>>(Wq, Wk, Wv, Wo, whi, wlo, wT);

    // (3) V GEMM (single-pass tf32)
    dim3 tgrid(DD / 128, MROWS / 128);
    gemm_tf32_kernel<<<tgrid, 256, TSMEM_TOTAL>>>(ao, wT, nullptr, qkv + 2 * MD);

    // (4) fused QK GEMM (bf16x3)  <-- ncu capture slot / clock control
    dim3 qkgrid(2 * DD / 128, MROWS / 128);
    gemm_bf16x3_kernel<<<qkgrid, 256, GSMEM_TOTAL>>>(ahi, alo, whi, wlo, nullptr, qkv);

    // (5) attention (HMMA S + HMMA PV): overwrites g_ao
    dim3 attn_grid(SS / BQ, HH, BB);
    attn_local_kernel<<<attn_grid, 256, ATT_SMEM_BYTES>>>(
        qkv, qkv + MD, qkv + 2 * MD, amask, ao);

    // (6) output projection (single-pass tf32)
    gemm_tf32_kernel<<<tgrid, 256, TSMEM_TOTAL>>>(ao, wT + (long)DD * DD, bo, out);
}